// round 1
// baseline (speedup 1.0000x reference)
#include <cuda_runtime.h>
#include <stdint.h>

#define NLAYERS 24
#define BATCH   512
#define RDIM    32
#define LQ      256
#define LOUT    257
#define NROWS   (NLAYERS*BATCH*RDIM)      /* 393216 rows of length 256/257 */
#define QOUT_ELEMS (NROWS*LOUT)           /* 101,056,512 */
#define QOUT4   (QOUT_ELEMS/4)            /* 25,264,128  */
#define NCOMPUTE 64
#define NCOPYB   2048
#define FULLMASK 0xffffffffu

// ---------------- scratch (static device globals; no allocation) ----------------
__device__ float2 g_wT [NLAYERS*32*128];   // [l][j][row] -> (w_past, w_h)   786 KB
__device__ float  g_f1T[NLAYERS*32*128];   // [l][j][k]                      393 KB
__device__ float  g_hseq[NROWS];           // h BEFORE each layer, [l][b][r] 1.5 MB

__device__ __forceinline__ float sigf(float v) { return 1.0f / (1.0f + __expf(-v)); }

// ---------------- K0: weight transposes for coalesced lane access ----------------
__global__ void prep_kernel(const float* __restrict__ conv_w,
                            const float* __restrict__ fc1_w) {
    int idx = blockIdx.x * blockDim.x + threadIdx.x;
    if (idx >= NLAYERS * 32 * 128) return;
    {
        // conv_w: [l][row(128)][j(32)][2]  (float2 index = (l*128+row)*32 + j)
        int l = idx / 4096, rem = idx & 4095, row = rem / 32, j = rem & 31;
        float2 v = ((const float2*)conv_w)[idx];
        g_wT[(l * 32 + j) * 128 + row] = v;
    }
    {
        // fc1_w: [k(128)][768];  dst [l][j][k]
        int l = idx / 4096, rem = idx & 4095, j = rem >> 7, k = rem & 127;
        g_f1T[idx] = fc1_w[k * 768 + l * 32 + j];
        (void)l; // layout: idx == (l*32+j)*128 + k
    }
}

// ---------------- K1: fused recurrence (blocks 0..63) + queue copy ----------------
__global__ void __launch_bounds__(128) main_kernel(
    const float* __restrict__ x,      const float* __restrict__ feat,
    const float* __restrict__ queues,
    const float* __restrict__ fc_h_w, const float* __restrict__ fc_h_b,
    const float* __restrict__ fc_c_w, const float* __restrict__ fc_c_b,
    const float* __restrict__ conv_b,
    const float* __restrict__ fc1_b,  const float* __restrict__ fc2_w,
    const float* __restrict__ fc2_b,
    float* __restrict__ out)
{
    if (blockIdx.x < NCOMPUTE) {
        // ---- compute path: 1 warp handles 2 batch elements; lane = R index ----
        int wid  = threadIdx.x >> 5;
        int lane = threadIdx.x & 31;
        int b0   = blockIdx.x * 8 + wid * 2;
        int b1   = b0 + 1;

        float h0v, h1v, c0v, c1v;
        {
            float ha0 = fc_h_b[lane], ca0 = fc_c_b[lane];
            float ha1 = ha0,          ca1 = ca0;
            #pragma unroll
            for (int i = 0; i < 9; i++) {
                float wh = fc_h_w[lane * 9 + i];
                float wc = fc_c_w[lane * 9 + i];
                float v0 = (i == 0) ? x[b0] : feat[b0 * 8 + i - 1];
                float v1 = (i == 0) ? x[b1] : feat[b1 * 8 + i - 1];
                ha0 += wh * v0; ca0 += wc * v0;
                ha1 += wh * v1; ca1 += wc * v1;
            }
            h0v = tanhf(ha0); c0v = tanhf(ca0);
            h1v = tanhf(ha1); c1v = tanhf(ca1);
        }
        g_hseq[(0 * BATCH + b0) * RDIM + lane] = h0v;
        g_hseq[(0 * BATCH + b1) * RDIM + lane] = h1v;

        float y00 = 0.f, y10 = 0.f, y20 = 0.f, y30 = 0.f;
        float y01 = 0.f, y11 = 0.f, y21 = 0.f, y31 = 0.f;

        #pragma unroll 1
        for (int l = 0; l < NLAYERS; l++) {
            int dil = 1 << (l & 7);
            float p0 = __ldg(queues + (size_t)((l * BATCH + b0) * RDIM + lane) * LQ + (LQ - dil));
            float p1 = __ldg(queues + (size_t)((l * BATCH + b1) * RDIM + lane) * LQ + (LQ - dil));

            float a00, a10, a20, a30, a01, a11, a21, a31;
            a00 = a01 = __ldg(conv_b + l * 128 +  0 + lane);
            a10 = a11 = __ldg(conv_b + l * 128 + 32 + lane);
            a20 = a21 = __ldg(conv_b + l * 128 + 64 + lane);
            a30 = a31 = __ldg(conv_b + l * 128 + 96 + lane);

            const float2* wp = g_wT + l * 32 * 128;
            #pragma unroll 8
            for (int j = 0; j < 32; j++) {
                float pj0 = __shfl_sync(FULLMASK, p0,  j);
                float pj1 = __shfl_sync(FULLMASK, p1,  j);
                float hj0 = __shfl_sync(FULLMASK, h0v, j);
                float hj1 = __shfl_sync(FULLMASK, h1v, j);
                float2 w0 = wp[j * 128 +  0 + lane];
                float2 w1 = wp[j * 128 + 32 + lane];
                float2 w2 = wp[j * 128 + 64 + lane];
                float2 w3 = wp[j * 128 + 96 + lane];
                a00 += w0.x * pj0 + w0.y * hj0;  a01 += w0.x * pj1 + w0.y * hj1;
                a10 += w1.x * pj0 + w1.y * hj0;  a11 += w1.x * pj1 + w1.y * hj1;
                a20 += w2.x * pj0 + w2.y * hj0;  a21 += w2.x * pj1 + w2.y * hj1;
                a30 += w3.x * pj0 + w3.y * hj0;  a31 += w3.x * pj1 + w3.y * hj1;
            }
            // gates: ig=a0, cf=a1, cg=a2, eg=a3
            c0v = sigf(a00) * c0v + tanhf(a10) * sigf(a20);
            h0v = sigf(a30) * tanhf(c0v);
            c1v = sigf(a01) * c1v + tanhf(a11) * sigf(a21);
            h1v = sigf(a31) * tanhf(c1v);

            if (l < NLAYERS - 1) {
                g_hseq[((l + 1) * BATCH + b0) * RDIM + lane] = h0v;
                g_hseq[((l + 1) * BATCH + b1) * RDIM + lane] = h1v;
            }

            // fc1 accumulation with skip[l] = new h
            const float* f1p = g_f1T + l * 32 * 128;
            #pragma unroll 8
            for (int j = 0; j < 32; j++) {
                float hj0 = __shfl_sync(FULLMASK, h0v, j);
                float hj1 = __shfl_sync(FULLMASK, h1v, j);
                float f0 = f1p[j * 128 +  0 + lane];
                float f1 = f1p[j * 128 + 32 + lane];
                float f2 = f1p[j * 128 + 64 + lane];
                float f3 = f1p[j * 128 + 96 + lane];
                y00 += f0 * hj0;  y01 += f0 * hj1;
                y10 += f1 * hj0;  y11 += f1 * hj1;
                y20 += f2 * hj0;  y21 += f2 * hj1;
                y30 += f3 * hj0;  y31 += f3 * hj1;
            }
        }

        // fc1 bias + relu, fc2 dot, warp-reduce
        float bb0 = fc1_b[ 0 + lane], bb1 = fc1_b[32 + lane];
        float bb2 = fc1_b[64 + lane], bb3 = fc1_b[96 + lane];
        float w20 = fc2_w[ 0 + lane], w21 = fc2_w[32 + lane];
        float w22 = fc2_w[64 + lane], w23 = fc2_w[96 + lane];
        float s0 = fmaxf(y00 + bb0, 0.f) * w20 + fmaxf(y10 + bb1, 0.f) * w21
                 + fmaxf(y20 + bb2, 0.f) * w22 + fmaxf(y30 + bb3, 0.f) * w23;
        float s1 = fmaxf(y01 + bb0, 0.f) * w20 + fmaxf(y11 + bb1, 0.f) * w21
                 + fmaxf(y21 + bb2, 0.f) * w22 + fmaxf(y31 + bb3, 0.f) * w23;
        #pragma unroll
        for (int off = 16; off > 0; off >>= 1) {
            s0 += __shfl_xor_sync(FULLMASK, s0, off);
            s1 += __shfl_xor_sync(FULLMASK, s1, off);
        }
        if (lane == 0) {
            out[b0] = s0 + fc2_b[0];
            out[b1] = s1 + fc2_b[0];
        }
    } else {
        // ---- copy path: queues (len-256 rows) -> out (len-257 rows), streaming ----
        float4* oq = (float4*)(out + BATCH);
        unsigned nthreads = (gridDim.x - NCOMPUTE) * 128u;
        unsigned tid0 = (blockIdx.x - NCOMPUTE) * 128u + threadIdx.x;
        for (unsigned i4 = tid0; i4 < (unsigned)QOUT4; i4 += nthreads) {
            unsigned e = i4 * 4u;
            float v0, v1, v2, v3;
            {
                unsigned ee = e + 0; unsigned row = ee / 257u; unsigned t = ee - row * 257u;
                v0 = (t < 256u) ? __ldcs(queues + (size_t)row * 256u + t) : 0.f;
            }
            {
                unsigned ee = e + 1; unsigned row = ee / 257u; unsigned t = ee - row * 257u;
                v1 = (t < 256u) ? __ldcs(queues + (size_t)row * 256u + t) : 0.f;
            }
            {
                unsigned ee = e + 2; unsigned row = ee / 257u; unsigned t = ee - row * 257u;
                v2 = (t < 256u) ? __ldcs(queues + (size_t)row * 256u + t) : 0.f;
            }
            {
                unsigned ee = e + 3; unsigned row = ee / 257u; unsigned t = ee - row * 257u;
                v3 = (t < 256u) ? __ldcs(queues + (size_t)row * 256u + t) : 0.f;
            }
            __stcs(oq + i4, make_float4(v0, v1, v2, v3));
        }
    }
}

// ---------------- K2: append h_seq column at t = 256 ----------------
__global__ void append_kernel(float* __restrict__ out) {
    int idx = blockIdx.x * blockDim.x + threadIdx.x;
    if (idx < NROWS) {
        out[BATCH + (size_t)idx * LOUT + 256] = g_hseq[idx];
    }
}

extern "C" void kernel_launch(void* const* d_in, const int* in_sizes, int n_in,
                              void* d_out, int out_size) {
    const float* x      = (const float*)d_in[0];
    const float* feat   = (const float*)d_in[1];
    const float* queues = (const float*)d_in[2];
    const float* fc_h_w = (const float*)d_in[3];
    const float* fc_h_b = (const float*)d_in[4];
    const float* fc_c_w = (const float*)d_in[5];
    const float* fc_c_b = (const float*)d_in[6];
    const float* conv_w = (const float*)d_in[7];
    const float* conv_b = (const float*)d_in[8];
    const float* fc1_w  = (const float*)d_in[9];
    const float* fc1_b  = (const float*)d_in[10];
    const float* fc2_w  = (const float*)d_in[11];
    const float* fc2_b  = (const float*)d_in[12];
    float* out = (float*)d_out;

    prep_kernel<<<(NLAYERS * 32 * 128 + 255) / 256, 256>>>(conv_w, fc1_w);
    main_kernel<<<NCOMPUTE + NCOPYB, 128>>>(x, feat, queues,
                                            fc_h_w, fc_h_b, fc_c_w, fc_c_b,
                                            conv_b, fc1_b, fc2_w, fc2_b, out);
    append_kernel<<<(NROWS + 255) / 256, 256>>>(out);
}

// round 2
// speedup vs baseline: 1.5840x; 1.5840x over previous
#include <cuda_runtime.h>
#include <stdint.h>

#define NLAYERS 24
#define BATCH   512
#define RDIM    32
#define LQ      256
#define LOUT    257
#define NROWS   (NLAYERS*BATCH*RDIM)      /* 393216 rows */
#define QOUT_ELEMS (NROWS*LOUT)           /* 101,056,512 */
#define QOUT4   (QOUT_ELEMS/4)            /* 25,264,128  */
#define NCOMPUTE 64                       /* 64 blocks x 8 warps = 512 batches */
#define NCOPYB   1984
#define ILP      8
#define FULLMASK 0xffffffffu

// ---------------- scratch (static device globals; no allocation) ----------------
__device__ float2 g_wT [NLAYERS*32*128];   // [l][j][row] -> (w_past, w_h)
__device__ float  g_f1T[NLAYERS*32*128];   // [l][j][k]

__device__ __forceinline__ float sigf(float v) { return 1.0f / (1.0f + __expf(-v)); }

// ---------------- K0: weight transposes for coalesced lane access ----------------
__global__ void prep_kernel(const float* __restrict__ conv_w,
                            const float* __restrict__ fc1_w) {
    int idx = blockIdx.x * blockDim.x + threadIdx.x;
    if (idx >= NLAYERS * 32 * 128) return;
    {
        // conv_w: [l][row(128)][j(32)][2]  (float2 index = (l*128+row)*32 + j)
        int l = idx / 4096, rem = idx & 4095, row = rem / 32, j = rem & 31;
        float2 v = ((const float2*)conv_w)[idx];
        g_wT[(l * 32 + j) * 128 + row] = v;
    }
    {
        // fc1_w: [k(128)][768];  dst [l][j][k], idx == (l*32+j)*128 + k
        int l = idx / 4096, rem = idx & 4095, j = rem >> 7, k = rem & 127;
        g_f1T[idx] = fc1_w[k * 768 + l * 32 + j];
    }
}

// ---------------- K1: fused recurrence + queue copy ----------------
__global__ void __launch_bounds__(256, 4) main_kernel(
    const float* __restrict__ x,      const float* __restrict__ feat,
    const float* __restrict__ queues,
    const float* __restrict__ fc_h_w, const float* __restrict__ fc_h_b,
    const float* __restrict__ fc_c_w, const float* __restrict__ fc_c_b,
    const float* __restrict__ conv_b,
    const float* __restrict__ fc1_b,  const float* __restrict__ fc2_w,
    const float* __restrict__ fc2_b,
    float* __restrict__ out)
{
    if (blockIdx.x < NCOMPUTE) {
        // ---- compute path: 1 warp = 1 batch element; lane = R index ----
        int warp = threadIdx.x >> 5;
        int lane = threadIdx.x & 31;
        int b    = blockIdx.x * 8 + warp;

        float h, c;
        {
            float ha = fc_h_b[lane], ca = fc_c_b[lane];
            #pragma unroll
            for (int i = 0; i < 9; i++) {
                float wh = fc_h_w[lane * 9 + i];
                float wc = fc_c_w[lane * 9 + i];
                float v  = (i == 0) ? x[b] : feat[b * 8 + i - 1];
                ha += wh * v; ca += wc * v;
            }
            h = tanhf(ha); c = tanhf(ca);
        }
        // h BEFORE layer 0 goes into the t=256 column of layer 0's queue rows
        out[BATCH + (size_t)((0 * BATCH + b) * RDIM + lane) * LOUT + 256] = h;

        float y0 = 0.f, y1 = 0.f, y2 = 0.f, y3 = 0.f;

        #pragma unroll 1
        for (int l = 0; l < NLAYERS; l++) {
            int dil = 1 << (l & 7);
            float p = __ldg(queues + (size_t)((l * BATCH + b) * RDIM + lane) * LQ + (LQ - dil));

            float a0 = __ldg(conv_b + l * 128 +  0 + lane);
            float a1 = __ldg(conv_b + l * 128 + 32 + lane);
            float a2 = __ldg(conv_b + l * 128 + 64 + lane);
            float a3 = __ldg(conv_b + l * 128 + 96 + lane);

            const float2* wp = g_wT + l * 32 * 128;
            #pragma unroll 8
            for (int j = 0; j < 32; j++) {
                float pj = __shfl_sync(FULLMASK, p, j);
                float hj = __shfl_sync(FULLMASK, h, j);
                float2 w0 = wp[j * 128 +  0 + lane];
                float2 w1 = wp[j * 128 + 32 + lane];
                float2 w2 = wp[j * 128 + 64 + lane];
                float2 w3 = wp[j * 128 + 96 + lane];
                a0 += w0.x * pj + w0.y * hj;
                a1 += w1.x * pj + w1.y * hj;
                a2 += w2.x * pj + w2.y * hj;
                a3 += w3.x * pj + w3.y * hj;
            }
            c = sigf(a0) * c + tanhf(a1) * sigf(a2);
            h = sigf(a3) * tanhf(c);

            if (l < NLAYERS - 1)
                out[BATCH + (size_t)(((l + 1) * BATCH + b) * RDIM + lane) * LOUT + 256] = h;

            const float* f1p = g_f1T + l * 32 * 128;
            #pragma unroll 8
            for (int j = 0; j < 32; j++) {
                float hj = __shfl_sync(FULLMASK, h, j);
                y0 += f1p[j * 128 +  0 + lane] * hj;
                y1 += f1p[j * 128 + 32 + lane] * hj;
                y2 += f1p[j * 128 + 64 + lane] * hj;
                y3 += f1p[j * 128 + 96 + lane] * hj;
            }
        }

        float s = fmaxf(y0 + fc1_b[ 0 + lane], 0.f) * fc2_w[ 0 + lane]
                + fmaxf(y1 + fc1_b[32 + lane], 0.f) * fc2_w[32 + lane]
                + fmaxf(y2 + fc1_b[64 + lane], 0.f) * fc2_w[64 + lane]
                + fmaxf(y3 + fc1_b[96 + lane], 0.f) * fc2_w[96 + lane];
        #pragma unroll
        for (int off = 16; off > 0; off >>= 1)
            s += __shfl_xor_sync(FULLMASK, s, off);
        if (lane == 0) out[b] = s + fc2_b[0];
    } else {
        // ---- copy path: queues (len-256 rows) -> out (len-257 rows) ----
        // out element e maps to queues[row*256 + t] where row=e/257, t=e%257,
        // t==256 column is written by the compute path (skip it here).
        float4* oq = (float4*)(out + BATCH);
        const unsigned stride = NCOPYB * 256u;
        unsigned t0 = (blockIdx.x - NCOMPUTE) * 256u + threadIdx.x;

        for (unsigned base = t0; base < (unsigned)QOUT4; base += stride * ILP) {
            unsigned idx[ILP];
            float4   v[ILP];
            bool     fast[ILP];
            bool     ok[ILP];
            #pragma unroll
            for (int k = 0; k < ILP; k++) {
                unsigned i4 = base + (unsigned)k * stride;
                idx[k] = i4;
                ok[k]  = (i4 < (unsigned)QOUT4);
                fast[k] = false;
                if (ok[k]) {
                    unsigned e   = i4 * 4u;
                    unsigned row = e / 257u;
                    unsigned t   = e - row * 257u;
                    if (t < 253u) {
                        fast[k] = true;
                        const float* src = queues + (size_t)row * 256u + t;
                        v[k].x = __ldcs(src + 0);
                        v[k].y = __ldcs(src + 1);
                        v[k].z = __ldcs(src + 2);
                        v[k].w = __ldcs(src + 3);
                    }
                }
            }
            #pragma unroll
            for (int k = 0; k < ILP; k++) {
                if (!ok[k]) continue;
                if (fast[k]) {
                    __stcs(oq + idx[k], v[k]);
                } else {
                    // row-wrap / t==256 slow path: per-element, skip t==256
                    unsigned e = idx[k] * 4u;
                    #pragma unroll
                    for (int j = 0; j < 4; j++) {
                        unsigned ee  = e + (unsigned)j;
                        unsigned r2  = ee / 257u;
                        unsigned t2  = ee - r2 * 257u;
                        if (t2 < 256u) {
                            float val = __ldcs(queues + (size_t)r2 * 256u + t2);
                            __stcs(out + BATCH + ee, val);
                        }
                    }
                }
            }
        }
    }
}

extern "C" void kernel_launch(void* const* d_in, const int* in_sizes, int n_in,
                              void* d_out, int out_size) {
    const float* x      = (const float*)d_in[0];
    const float* feat   = (const float*)d_in[1];
    const float* queues = (const float*)d_in[2];
    const float* fc_h_w = (const float*)d_in[3];
    const float* fc_h_b = (const float*)d_in[4];
    const float* fc_c_w = (const float*)d_in[5];
    const float* fc_c_b = (const float*)d_in[6];
    const float* conv_w = (const float*)d_in[7];
    const float* conv_b = (const float*)d_in[8];
    const float* fc1_w  = (const float*)d_in[9];
    const float* fc1_b  = (const float*)d_in[10];
    const float* fc2_w  = (const float*)d_in[11];
    const float* fc2_b  = (const float*)d_in[12];
    float* out = (float*)d_out;

    prep_kernel<<<(NLAYERS * 32 * 128 + 255) / 256, 256>>>(conv_w, fc1_w);
    main_kernel<<<NCOMPUTE + NCOPYB, 256>>>(x, feat, queues,
                                            fc_h_w, fc_h_b, fc_c_w, fc_c_b,
                                            conv_b, fc1_b, fc2_w, fc2_b, out);
}